// round 1
// baseline (speedup 1.0000x reference)
#include <cuda_runtime.h>
#include <math.h>

#define TOKENS 4096
#define DIM    1024
#define QKV_N  3072
#define NH     16
#define HD     64
#define TSEQ   2048
#define BHEADS 32
#define ATT_SCALE 0.125f

// Scratch (static device globals — no allocation in kernel_launch)
__device__ float g_qkv[TOKENS * QKV_N];          // 50 MB
__device__ float g_q[BHEADS * TSEQ * HD];        // 16.8 MB, [bh][t][d] (roped)
__device__ float g_k[BHEADS * TSEQ * HD];
__device__ float g_v[BHEADS * TSEQ * HD];
__device__ float g_o[TOKENS * DIM];              // token-major [b*T+t][h*64+d]

// ---------------------------------------------------------------------------
// Tiled fp32 SGEMM: C[M,N] = A[M,K] @ B[K,N] (+ bias[N] if non-null)
// BM=BN=128, BK=8, 8x8 per thread, 256 threads. M%128==N%128==K%8==0 assumed.
// ---------------------------------------------------------------------------
__global__ __launch_bounds__(256)
void sgemm128(const float* __restrict__ A, const float* __restrict__ B,
              float* __restrict__ C, const float* __restrict__ bias,
              int M, int N, int K)
{
    const int BM = 128, BN = 128, BK = 8, TM = 8, TN = 8;
    __shared__ float As[BK][BM];
    __shared__ float Bs[BK][BN];

    const int tid  = threadIdx.x;
    const int tr   = tid >> 4;          // 0..15
    const int tc   = tid & 15;          // 0..15
    const int brow = blockIdx.y, bcol = blockIdx.x;

    const int aRow = tid >> 1;          // 0..127
    const int aCol = (tid & 1) << 2;    // 0 or 4
    const int bRow = tid >> 5;          // 0..7
    const int bCol = (tid & 31) << 2;   // 0..124

    const float* Ag = A + (size_t)brow * BM * K;
    const float* Bg = B + bcol * BN;

    float acc[TM][TN];
    #pragma unroll
    for (int i = 0; i < TM; i++)
        #pragma unroll
        for (int j = 0; j < TN; j++) acc[i][j] = 0.f;

    for (int k0 = 0; k0 < K; k0 += BK) {
        float4 av = *(const float4*)(Ag + (size_t)aRow * K + k0 + aCol);
        As[aCol + 0][aRow] = av.x;
        As[aCol + 1][aRow] = av.y;
        As[aCol + 2][aRow] = av.z;
        As[aCol + 3][aRow] = av.w;
        float4 bv = *(const float4*)(Bg + (size_t)(k0 + bRow) * N + bCol);
        *(float4*)&Bs[bRow][bCol] = bv;
        __syncthreads();

        #pragma unroll
        for (int kk = 0; kk < BK; kk++) {
            float ar[TM], br[TN];
            #pragma unroll
            for (int i = 0; i < TM; i++) ar[i] = As[kk][tr * TM + i];
            #pragma unroll
            for (int j = 0; j < TN; j++) br[j] = Bs[kk][tc * TN + j];
            #pragma unroll
            for (int i = 0; i < TM; i++)
                #pragma unroll
                for (int j = 0; j < TN; j++)
                    acc[i][j] = fmaf(ar[i], br[j], acc[i][j]);
        }
        __syncthreads();
    }

    float badd[TN];
    #pragma unroll
    for (int j = 0; j < TN; j++)
        badd[j] = bias ? bias[bcol * BN + tc * TN + j] : 0.f;

    float* Cg = C + (size_t)brow * BM * N + bcol * BN;
    #pragma unroll
    for (int i = 0; i < TM; i++) {
        #pragma unroll
        for (int j = 0; j < TN; j += 4) {
            float4 v;
            v.x = acc[i][j + 0] + badd[j + 0];
            v.y = acc[i][j + 1] + badd[j + 1];
            v.z = acc[i][j + 2] + badd[j + 2];
            v.w = acc[i][j + 3] + badd[j + 3];
            *(float4*)(Cg + (size_t)(tr * TM + i) * N + tc * TN + j) = v;
        }
    }
}

// ---------------------------------------------------------------------------
// RoPE + split qkv[4096,3072] -> g_q/g_k/g_v in [bh][t][64], rope on q,k.
// One warp per (bh, t); lane = rotation index i in [0,32).
// ---------------------------------------------------------------------------
__global__ __launch_bounds__(256)
void rope_split_kernel()
{
    int gw   = (blockIdx.x * blockDim.x + threadIdx.x) >> 5;
    int lane = threadIdx.x & 31;
    if (gw >= BHEADS * TSEQ) return;
    int bh = gw >> 11;            // / 2048
    int t  = gw & 2047;
    int b  = bh >> 4, h = bh & 15;

    const float* row = g_qkv + ((size_t)(b * TSEQ + t)) * QKV_N + h * HD;

    // freqs = exp(-ln(10000) * i / 32)
    float freq = expf(-9.210340371976184f * (float)lane * (1.0f / 32.0f));
    float ang  = (float)t * freq;
    float s, c;
    sincosf(ang, &s, &c);

    size_t obase = ((size_t)bh * TSEQ + t) * HD;

    float q1 = row[lane], q2 = row[lane + 32];
    g_q[obase + lane]      = q1 * c - q2 * s;
    g_q[obase + lane + 32] = q1 * s + q2 * c;

    float k1 = row[DIM + lane], k2 = row[DIM + lane + 32];
    g_k[obase + lane]      = k1 * c - k2 * s;
    g_k[obase + lane + 32] = k1 * s + k2 * c;

    g_v[obase + lane]      = row[2 * DIM + lane];
    g_v[obase + lane + 32] = row[2 * DIM + lane + 32];
}

// ---------------------------------------------------------------------------
// Causal flash attention, fp32, online softmax.
// Block: 256 threads = 8 warps; each warp owns 8 query rows (BQ=64/block).
// Each row handled by 4 lanes; each lane owns 16 accumulator dims.
// K/V staged in SMEM in BK=32 tiles. O written token-major into g_o.
// ---------------------------------------------------------------------------
__global__ __launch_bounds__(256)
void flash_attn_kernel()
{
    const int BQ = 64, BK = 32;
    int bh = blockIdx.y;
    int q0 = blockIdx.x * BQ;
    const float* Qh = g_q + (size_t)bh * TSEQ * HD;
    const float* Kh = g_k + (size_t)bh * TSEQ * HD;
    const float* Vh = g_v + (size_t)bh * TSEQ * HD;

    __shared__ float Ks[BK][HD];
    __shared__ float Vs[BK][HD];

    int tid  = threadIdx.x;
    int lane = tid & 31;
    int warp = tid >> 5;
    int row  = warp * 8 + (lane >> 2);   // 0..63 within tile
    int sub  = lane & 3;                 // which 16-dim slice
    int qrow = q0 + row;

    float qf[16];
    {
        const float* qp = Qh + (size_t)qrow * HD + sub * 16;
        #pragma unroll
        for (int i = 0; i < 16; i += 4) {
            float4 v = *(const float4*)(qp + i);
            qf[i] = v.x; qf[i + 1] = v.y; qf[i + 2] = v.z; qf[i + 3] = v.w;
        }
    }

    float acc[16];
    #pragma unroll
    for (int i = 0; i < 16; i++) acc[i] = 0.f;
    float m = -INFINITY, l = 0.f;

    // tile-load mapping: 256 threads load 32x64 floats (8 floats each)
    int lr = tid >> 3;           // 0..31
    int lc = (tid & 7) << 3;     // 0,8,...,56

    int kend = q0 + BQ;
    for (int k0 = 0; k0 < kend; k0 += BK) {
        {
            const float* kp = Kh + (size_t)(k0 + lr) * HD + lc;
            const float* vp = Vh + (size_t)(k0 + lr) * HD + lc;
            *(float4*)&Ks[lr][lc]     = *(const float4*)(kp);
            *(float4*)&Ks[lr][lc + 4] = *(const float4*)(kp + 4);
            *(float4*)&Vs[lr][lc]     = *(const float4*)(vp);
            *(float4*)&Vs[lr][lc + 4] = *(const float4*)(vp + 4);
        }
        __syncthreads();

        // partial dot products over this lane's 16 dims, then 4-lane reduce
        float s[BK];
        #pragma unroll
        for (int j = 0; j < BK; j++) {
            float p = 0.f;
            #pragma unroll
            for (int i = 0; i < 16; i++)
                p = fmaf(qf[i], Ks[j][sub * 16 + i], p);
            s[j] = p;
        }
        #pragma unroll
        for (int j = 0; j < BK; j++) {
            s[j] += __shfl_xor_sync(0xffffffffu, s[j], 1);
            s[j] += __shfl_xor_sync(0xffffffffu, s[j], 2);
            s[j] *= ATT_SCALE;
        }

        // causal mask (only needed on tail tiles for this row)
        if (k0 + BK - 1 > qrow) {
            #pragma unroll
            for (int j = 0; j < BK; j++)
                if (k0 + j > qrow) s[j] = -INFINITY;
        }

        float tmax = -INFINITY;
        #pragma unroll
        for (int j = 0; j < BK; j++) tmax = fmaxf(tmax, s[j]);
        float mnew    = fmaxf(m, tmax);
        float rescale = __expf(m - mnew);   // first tile: exp(-inf)=0
        float lsum = 0.f;
        #pragma unroll
        for (int j = 0; j < BK; j++) {
            float p = __expf(s[j] - mnew);  // masked: exp(-inf)=0
            s[j] = p;
            lsum += p;
        }
        l = l * rescale + lsum;
        #pragma unroll
        for (int i = 0; i < 16; i++) acc[i] *= rescale;
        #pragma unroll
        for (int j = 0; j < BK; j++) {
            #pragma unroll
            for (int i = 0; i < 16; i++)
                acc[i] = fmaf(s[j], Vs[j][sub * 16 + i], acc[i]);
        }
        m = mnew;
        __syncthreads();
    }

    float inv = 1.0f / l;
    int b = bh >> 4, h = bh & 15;
    float* op = g_o + ((size_t)(b * TSEQ) + qrow) * DIM + h * HD + sub * 16;
    #pragma unroll
    for (int i = 0; i < 16; i += 4) {
        float4 v;
        v.x = acc[i] * inv; v.y = acc[i + 1] * inv;
        v.z = acc[i + 2] * inv; v.w = acc[i + 3] * inv;
        *(float4*)(op + i) = v;
    }
}

// ---------------------------------------------------------------------------
extern "C" void kernel_launch(void* const* d_in, const int* in_sizes, int n_in,
                              void* d_out, int out_size)
{
    const float* x      = (const float*)d_in[0];
    const float* w_qkv  = (const float*)d_in[1];
    const float* w_proj = (const float*)d_in[2];
    const float* b_proj = (const float*)d_in[3];
    float* out = (float*)d_out;

    float *qkv_p = nullptr, *o_p = nullptr;
    cudaGetSymbolAddress((void**)&qkv_p, g_qkv);
    cudaGetSymbolAddress((void**)&o_p, g_o);

    // 1) qkv = x @ w_qkv   [4096,1024]x[1024,3072]
    dim3 g1(QKV_N / 128, TOKENS / 128);
    sgemm128<<<g1, 256>>>(x, w_qkv, qkv_p, nullptr, TOKENS, QKV_N, DIM);

    // 2) rope + split into [bh][t][64]
    int nwarps = BHEADS * TSEQ;
    rope_split_kernel<<<(nwarps * 32 + 255) / 256, 256>>>();

    // 3) causal flash attention -> g_o (token-major)
    flash_attn_kernel<<<dim3(TSEQ / 64, BHEADS), 256>>>();

    // 4) out = g_o @ w_proj + b_proj
    dim3 g2(DIM / 128, TOKENS / 128);
    sgemm128<<<g2, 256>>>(o_p, w_proj, out, b_proj, TOKENS, DIM, DIM);
}

// round 2
// speedup vs baseline: 2.1604x; 2.1604x over previous
#include <cuda_runtime.h>
#include <math.h>

#define TOKENS 4096
#define DIM    1024
#define QKV_N  3072
#define NH     16
#define HD     64
#define TSEQ   2048
#define BHEADS 32
#define ATT_SCALE 0.125f

// Scratch (static device globals — no allocation in kernel_launch)
__device__ float g_qkv[TOKENS * QKV_N];
__device__ float g_q[BHEADS * TSEQ * HD];   // [bh][t][d] roped
__device__ float g_k[BHEADS * TSEQ * HD];
__device__ float g_v[BHEADS * TSEQ * HD];
__device__ float g_o[TOKENS * DIM];         // token-major

// ---------------------------------------------------------------------------
// Tiled fp32 SGEMM: C[M,N] = A[M,K] @ B[K,N] (+ bias)
// ---------------------------------------------------------------------------
__global__ __launch_bounds__(256)
void sgemm128(const float* __restrict__ A, const float* __restrict__ B,
              float* __restrict__ C, const float* __restrict__ bias,
              int M, int N, int K)
{
    const int BM = 128, BN = 128, BK = 8, TM = 8, TN = 8;
    __shared__ float As[BK][BM];
    __shared__ float Bs[BK][BN];

    const int tid  = threadIdx.x;
    const int tr   = tid >> 4;
    const int tc   = tid & 15;
    const int brow = blockIdx.y, bcol = blockIdx.x;

    const int aRow = tid >> 1;
    const int aCol = (tid & 1) << 2;
    const int bRow = tid >> 5;
    const int bCol = (tid & 31) << 2;

    const float* Ag = A + (size_t)brow * BM * K;
    const float* Bg = B + bcol * BN;

    float acc[TM][TN];
    #pragma unroll
    for (int i = 0; i < TM; i++)
        #pragma unroll
        for (int j = 0; j < TN; j++) acc[i][j] = 0.f;

    for (int k0 = 0; k0 < K; k0 += BK) {
        float4 av = *(const float4*)(Ag + (size_t)aRow * K + k0 + aCol);
        As[aCol + 0][aRow] = av.x;
        As[aCol + 1][aRow] = av.y;
        As[aCol + 2][aRow] = av.z;
        As[aCol + 3][aRow] = av.w;
        float4 bv = *(const float4*)(Bg + (size_t)(k0 + bRow) * N + bCol);
        *(float4*)&Bs[bRow][bCol] = bv;
        __syncthreads();

        #pragma unroll
        for (int kk = 0; kk < BK; kk++) {
            float ar[TM], br[TN];
            #pragma unroll
            for (int i = 0; i < TM; i++) ar[i] = As[kk][tr * TM + i];
            #pragma unroll
            for (int j = 0; j < TN; j++) br[j] = Bs[kk][tc * TN + j];
            #pragma unroll
            for (int i = 0; i < TM; i++)
                #pragma unroll
                for (int j = 0; j < TN; j++)
                    acc[i][j] = fmaf(ar[i], br[j], acc[i][j]);
        }
        __syncthreads();
    }

    float badd[TN];
    #pragma unroll
    for (int j = 0; j < TN; j++)
        badd[j] = bias ? bias[bcol * BN + tc * TN + j] : 0.f;

    float* Cg = C + (size_t)brow * BM * N + bcol * BN;
    #pragma unroll
    for (int i = 0; i < TM; i++) {
        #pragma unroll
        for (int j = 0; j < TN; j += 4) {
            float4 v;
            v.x = acc[i][j + 0] + badd[j + 0];
            v.y = acc[i][j + 1] + badd[j + 1];
            v.z = acc[i][j + 2] + badd[j + 2];
            v.w = acc[i][j + 3] + badd[j + 3];
            *(float4*)(Cg + (size_t)(tr * TM + i) * N + tc * TN + j) = v;
        }
    }
}

// ---------------------------------------------------------------------------
// RoPE + split
// ---------------------------------------------------------------------------
__global__ __launch_bounds__(256)
void rope_split_kernel()
{
    int gw   = (blockIdx.x * blockDim.x + threadIdx.x) >> 5;
    int lane = threadIdx.x & 31;
    if (gw >= BHEADS * TSEQ) return;
    int bh = gw >> 11;
    int t  = gw & 2047;
    int b  = bh >> 4, h = bh & 15;

    const float* row = g_qkv + ((size_t)(b * TSEQ + t)) * QKV_N + h * HD;

    float freq = expf(-9.210340371976184f * (float)lane * (1.0f / 32.0f));
    float ang  = (float)t * freq;
    float s, c;
    sincosf(ang, &s, &c);

    size_t obase = ((size_t)bh * TSEQ + t) * HD;

    float q1 = row[lane], q2 = row[lane + 32];
    g_q[obase + lane]      = q1 * c - q2 * s;
    g_q[obase + lane + 32] = q1 * s + q2 * c;

    float k1 = row[DIM + lane], k2 = row[DIM + lane + 32];
    g_k[obase + lane]      = k1 * c - k2 * s;
    g_k[obase + lane + 32] = k1 * s + k2 * c;

    g_v[obase + lane]      = row[2 * DIM + lane];
    g_v[obase + lane + 32] = row[2 * DIM + lane + 32];
}

// ---------------------------------------------------------------------------
// Flash attention v2: BQ=128, BK=64, 256 threads.
// S = Q@K^T as register-tiled GEMM (8 rows x 4 cols per thread),
// softmax reduced via shfl across the 16 col-lanes, P staged in smem,
// O += P@V as second register-tiled GEMM.
// ---------------------------------------------------------------------------
#define FA_BQ 128
#define FA_BK 64
#define PSS   68   // Ps row stride (pad)

// smem layout (floats): Qs[64][128] | Ks[64][64] | Vs[64][64] | Ps[128][68]
#define FA_SMEM_FLOATS (64*128 + 64*64 + 64*64 + 128*PSS)

extern __shared__ float fa_smem[];

__global__ __launch_bounds__(256)
void flash_attn2()
{
    float* Qs = fa_smem;             // [d][r]  64 x 128
    float* Ks = Qs + 64 * 128;       // [d][j]  64 x 64
    float* Vs = Ks + 64 * 64;        // [j][d]  64 x 64
    float* Ps = Vs + 64 * 64;        // [r][j]  128 x PSS

    const int bh   = blockIdx.y;
    const int qblk = gridDim.x - 1 - blockIdx.x;   // heavy blocks first
    const int q0   = qblk * FA_BQ;

    const float* Qh = g_q + (size_t)bh * TSEQ * HD;
    const float* Kh = g_k + (size_t)bh * TSEQ * HD;
    const float* Vh = g_v + (size_t)bh * TSEQ * HD;

    const int tid = threadIdx.x;
    const int tr  = tid >> 4;    // 0..15, owns rows tr*8..tr*8+7
    const int tc  = tid & 15;    // 0..15, owns cols tc*4..tc*4+3

    // Load Q tile transposed: Qs[d][r]
    {
        int r     = tid >> 1;
        int dbase = (tid & 1) * 32;
        const float* qp = Qh + (size_t)(q0 + r) * HD + dbase;
        #pragma unroll
        for (int j = 0; j < 32; j += 4) {
            float4 v = *(const float4*)(qp + j);
            Qs[(dbase + j + 0) * 128 + r] = v.x;
            Qs[(dbase + j + 1) * 128 + r] = v.y;
            Qs[(dbase + j + 2) * 128 + r] = v.z;
            Qs[(dbase + j + 3) * 128 + r] = v.w;
        }
    }

    float oacc[8][4];
    float m[8], l[8];
    #pragma unroll
    for (int i = 0; i < 8; i++) {
        m[i] = -INFINITY; l[i] = 0.f;
        #pragma unroll
        for (int j = 0; j < 4; j++) oacc[i][j] = 0.f;
    }

    const int ntiles = 2 * qblk + 2;
    for (int t = 0; t < ntiles; t++) {
        const int k0 = t * FA_BK;

        // Load K tile transposed (Ks[d][j]) and V tile straight (Vs[j][d])
        {
            int j     = tid >> 2;
            int dbase = (tid & 3) * 16;
            const float* kp = Kh + (size_t)(k0 + j) * HD + dbase;
            const float* vp = Vh + (size_t)(k0 + j) * HD + dbase;
            #pragma unroll
            for (int d = 0; d < 16; d += 4) {
                float4 kv = *(const float4*)(kp + d);
                Ks[(dbase + d + 0) * 64 + j] = kv.x;
                Ks[(dbase + d + 1) * 64 + j] = kv.y;
                Ks[(dbase + d + 2) * 64 + j] = kv.z;
                Ks[(dbase + d + 3) * 64 + j] = kv.w;
                *(float4*)(Vs + j * 64 + dbase + d) = *(const float4*)(vp + d);
            }
        }
        __syncthreads();

        // ---- S = Q @ K^T (8x4 per thread) ----
        float sacc[8][4];
        #pragma unroll
        for (int i = 0; i < 8; i++)
            #pragma unroll
            for (int j = 0; j < 4; j++) sacc[i][j] = 0.f;

        #pragma unroll 8
        for (int kk = 0; kk < 64; kk++) {
            float4 qa = *(const float4*)(Qs + kk * 128 + tr * 8);
            float4 qb = *(const float4*)(Qs + kk * 128 + tr * 8 + 4);
            float4 kr = *(const float4*)(Ks + kk * 64 + tc * 4);
            float qr[8] = {qa.x, qa.y, qa.z, qa.w, qb.x, qb.y, qb.z, qb.w};
            float kc[4] = {kr.x, kr.y, kr.z, kr.w};
            #pragma unroll
            for (int i = 0; i < 8; i++)
                #pragma unroll
                for (int j = 0; j < 4; j++)
                    sacc[i][j] = fmaf(qr[i], kc[j], sacc[i][j]);
        }

        // ---- scale + causal mask ----
        const bool need_mask = (k0 + FA_BK - 1 > q0);
        #pragma unroll
        for (int i = 0; i < 8; i++) {
            int grow = q0 + tr * 8 + i;
            #pragma unroll
            for (int j = 0; j < 4; j++) {
                float s = sacc[i][j] * ATT_SCALE;
                if (need_mask && (k0 + tc * 4 + j > grow)) s = -INFINITY;
                sacc[i][j] = s;
            }
        }

        // ---- online softmax (per row, reduced across 16 tc lanes) ----
        #pragma unroll
        for (int i = 0; i < 8; i++) {
            float rmax = fmaxf(fmaxf(sacc[i][0], sacc[i][1]),
                               fmaxf(sacc[i][2], sacc[i][3]));
            rmax = fmaxf(rmax, __shfl_xor_sync(0xffffffffu, rmax, 1));
            rmax = fmaxf(rmax, __shfl_xor_sync(0xffffffffu, rmax, 2));
            rmax = fmaxf(rmax, __shfl_xor_sync(0xffffffffu, rmax, 4));
            rmax = fmaxf(rmax, __shfl_xor_sync(0xffffffffu, rmax, 8));

            float mnew = fmaxf(m[i], rmax);
            float resc = __expf(m[i] - mnew);
            m[i] = mnew;

            float p0 = __expf(sacc[i][0] - mnew);
            float p1 = __expf(sacc[i][1] - mnew);
            float p2 = __expf(sacc[i][2] - mnew);
            float p3 = __expf(sacc[i][3] - mnew);
            float psum = (p0 + p1) + (p2 + p3);
            psum += __shfl_xor_sync(0xffffffffu, psum, 1);
            psum += __shfl_xor_sync(0xffffffffu, psum, 2);
            psum += __shfl_xor_sync(0xffffffffu, psum, 4);
            psum += __shfl_xor_sync(0xffffffffu, psum, 8);

            l[i] = l[i] * resc + psum;
            #pragma unroll
            for (int j = 0; j < 4; j++) oacc[i][j] *= resc;

            float4 pv = make_float4(p0, p1, p2, p3);
            *(float4*)(Ps + (tr * 8 + i) * PSS + tc * 4) = pv;
        }
        __syncthreads();

        // ---- O += P @ V (8 rows x 4 dims per thread) ----
        #pragma unroll 4
        for (int j = 0; j < 64; j++) {
            float4 v = *(const float4*)(Vs + j * 64 + tc * 4);
            #pragma unroll
            for (int i = 0; i < 8; i++) {
                float p = Ps[(tr * 8 + i) * PSS + j];
                oacc[i][0] = fmaf(p, v.x, oacc[i][0]);
                oacc[i][1] = fmaf(p, v.y, oacc[i][1]);
                oacc[i][2] = fmaf(p, v.z, oacc[i][2]);
                oacc[i][3] = fmaf(p, v.w, oacc[i][3]);
            }
        }
        __syncthreads();
    }

    // ---- epilogue: normalize and write token-major ----
    const int b = bh >> 4, h = bh & 15;
    #pragma unroll
    for (int i = 0; i < 8; i++) {
        float inv = 1.0f / l[i];
        int grow = q0 + tr * 8 + i;
        float* op = g_o + ((size_t)(b * TSEQ) + grow) * DIM + h * HD + tc * 4;
        float4 v;
        v.x = oacc[i][0] * inv;
        v.y = oacc[i][1] * inv;
        v.z = oacc[i][2] * inv;
        v.w = oacc[i][3] * inv;
        *(float4*)op = v;
    }
}

// ---------------------------------------------------------------------------
extern "C" void kernel_launch(void* const* d_in, const int* in_sizes, int n_in,
                              void* d_out, int out_size)
{
    const float* x      = (const float*)d_in[0];
    const float* w_qkv  = (const float*)d_in[1];
    const float* w_proj = (const float*)d_in[2];
    const float* b_proj = (const float*)d_in[3];
    float* out = (float*)d_out;

    float *qkv_p = nullptr, *o_p = nullptr;
    cudaGetSymbolAddress((void**)&qkv_p, g_qkv);
    cudaGetSymbolAddress((void**)&o_p, g_o);

    // 1) qkv = x @ w_qkv
    dim3 g1(QKV_N / 128, TOKENS / 128);
    sgemm128<<<g1, 256>>>(x, w_qkv, qkv_p, nullptr, TOKENS, QKV_N, DIM);

    // 2) rope + split
    int nwarps = BHEADS * TSEQ;
    rope_split_kernel<<<(nwarps * 32 + 255) / 256, 256>>>();

    // 3) flash attention
    static int fa_attr_set = 0;
    size_t fa_smem_bytes = FA_SMEM_FLOATS * sizeof(float);
    if (!fa_attr_set) {
        cudaFuncSetAttribute(flash_attn2,
                             cudaFuncAttributeMaxDynamicSharedMemorySize,
                             (int)fa_smem_bytes);
        fa_attr_set = 1;
    }
    flash_attn2<<<dim3(TSEQ / FA_BQ, BHEADS), 256, fa_smem_bytes>>>();

    // 4) out = g_o @ w_proj + b_proj
    dim3 g2(DIM / 128, TOKENS / 128);
    sgemm128<<<g2, 256>>>(o_p, w_proj, out, b_proj, TOKENS, DIM, DIM);
}

// round 3
// speedup vs baseline: 2.2383x; 1.0360x over previous
#include <cuda_runtime.h>
#include <math.h>

#define TOKENS 4096
#define DIM    1024
#define QKV_N  3072
#define NH     16
#define HD     64
#define TSEQ   2048
#define BHEADS 32
#define ATT_SCALE 0.125f

// Scratch (static device globals — no allocation in kernel_launch)
__device__ float g_q[BHEADS * TSEQ * HD];   // [bh][t][d]
__device__ float g_k[BHEADS * TSEQ * HD];
__device__ float g_v[BHEADS * TSEQ * HD];
__device__ float g_o[TOKENS * DIM];         // token-major

// ---------------------------------------------------------------------------
// Double-buffered fp32 SGEMM: 128x128 tile, BK=16, 8x8 per thread, 256 thr.
// qkv_epi=0: C = A@B (+bias). qkv_epi=1: scatter into g_q/g_k/g_v per-head.
// ---------------------------------------------------------------------------
__global__ __launch_bounds__(256, 2)
void sgemm_db(const float* __restrict__ A, const float* __restrict__ B,
              float* __restrict__ C, const float* __restrict__ bias,
              int N, int K, int qkv_epi)
{
    __shared__ float As[2][16][128];
    __shared__ float Bs[2][16][128];

    const int tid  = threadIdx.x;
    const int tr   = tid >> 4;
    const int tc   = tid & 15;
    const int brow = blockIdx.y, bcol = blockIdx.x;

    // A: each thread loads row a_r (0..127), 8 cols starting at a_c (0 or 8)
    const int a_r = tid >> 1;
    const int a_c = (tid & 1) * 8;
    // B: each thread loads row b_r (0..15), 8 cols starting at b_c
    const int b_r = tid >> 4;
    const int b_c = (tid & 15) * 8;

    const float* Aptr = A + ((size_t)(brow * 128 + a_r)) * K + a_c;
    const float* Bptr = B + (size_t)b_r * N + bcol * 128 + b_c;

    float4 a0, a1, b0, b1;

    // prologue: load k0=0, fill buffer 0
    a0 = *(const float4*)(Aptr);
    a1 = *(const float4*)(Aptr + 4);
    b0 = *(const float4*)(Bptr);
    b1 = *(const float4*)(Bptr + 4);

    As[0][a_c + 0][a_r] = a0.x;
    As[0][a_c + 1][a_r] = a0.y;
    As[0][a_c + 2][a_r] = a0.z;
    As[0][a_c + 3][a_r] = a0.w;
    As[0][a_c + 4][a_r] = a1.x;
    As[0][a_c + 5][a_r] = a1.y;
    As[0][a_c + 6][a_r] = a1.z;
    As[0][a_c + 7][a_r] = a1.w;
    *(float4*)&Bs[0][b_r][b_c]     = b0;
    *(float4*)&Bs[0][b_r][b_c + 4] = b1;
    __syncthreads();

    float acc[8][8];
    #pragma unroll
    for (int i = 0; i < 8; i++)
        #pragma unroll
        for (int j = 0; j < 8; j++) acc[i][j] = 0.f;

    int buf = 0;
    for (int k0 = 0; k0 < K; k0 += 16) {
        const bool more = (k0 + 16 < K);
        if (more) {
            a0 = *(const float4*)(Aptr + k0 + 16);
            a1 = *(const float4*)(Aptr + k0 + 20);
            b0 = *(const float4*)(Bptr + (size_t)(k0 + 16) * N);
            b1 = *(const float4*)(Bptr + (size_t)(k0 + 16) * N + 4);
        }

        #pragma unroll
        for (int kk = 0; kk < 16; kk++) {
            float4 xa = *(const float4*)&As[buf][kk][tr * 8];
            float4 xb = *(const float4*)&As[buf][kk][tr * 8 + 4];
            float4 ya = *(const float4*)&Bs[buf][kk][tc * 8];
            float4 yb = *(const float4*)&Bs[buf][kk][tc * 8 + 4];
            float ar[8] = {xa.x, xa.y, xa.z, xa.w, xb.x, xb.y, xb.z, xb.w};
            float br[8] = {ya.x, ya.y, ya.z, ya.w, yb.x, yb.y, yb.z, yb.w};
            #pragma unroll
            for (int i = 0; i < 8; i++)
                #pragma unroll
                for (int j = 0; j < 8; j++)
                    acc[i][j] = fmaf(ar[i], br[j], acc[i][j]);
        }

        if (more) {
            const int nb = buf ^ 1;
            As[nb][a_c + 0][a_r] = a0.x;
            As[nb][a_c + 1][a_r] = a0.y;
            As[nb][a_c + 2][a_r] = a0.z;
            As[nb][a_c + 3][a_r] = a0.w;
            As[nb][a_c + 4][a_r] = a1.x;
            As[nb][a_c + 5][a_r] = a1.y;
            As[nb][a_c + 6][a_r] = a1.z;
            As[nb][a_c + 7][a_r] = a1.w;
            *(float4*)&Bs[nb][b_r][b_c]     = b0;
            *(float4*)&Bs[nb][b_r][b_c + 4] = b1;
        }
        buf ^= 1;
        __syncthreads();
    }

    if (!qkv_epi) {
        float badd[8];
        #pragma unroll
        for (int j = 0; j < 8; j++)
            badd[j] = bias ? bias[bcol * 128 + tc * 8 + j] : 0.f;

        float* Cg = C + (size_t)brow * 128 * N + bcol * 128;
        #pragma unroll
        for (int i = 0; i < 8; i++) {
            #pragma unroll
            for (int j = 0; j < 8; j += 4) {
                float4 v;
                v.x = acc[i][j + 0] + badd[j + 0];
                v.y = acc[i][j + 1] + badd[j + 1];
                v.z = acc[i][j + 2] + badd[j + 2];
                v.w = acc[i][j + 3] + badd[j + 3];
                *(float4*)(Cg + (size_t)(tr * 8 + i) * N + tc * 8 + j) = v;
            }
        }
    } else {
        // scatter into g_q / g_k / g_v with layout [bh][t][64]
        #pragma unroll
        for (int i = 0; i < 8; i++) {
            const int m_g = brow * 128 + tr * 8 + i;
            const int b   = m_g >> 11;
            const int t   = m_g & 2047;
            #pragma unroll
            for (int j = 0; j < 8; j += 4) {
                const int n_g   = bcol * 128 + tc * 8 + j;
                const int which = n_g >> 10;        // 0=q 1=k 2=v
                const int rmod  = n_g & 1023;
                const int h     = rmod >> 6;
                const int d     = rmod & 63;
                float* base = (which == 0) ? g_q : (which == 1) ? g_k : g_v;
                float4 v;
                v.x = acc[i][j + 0];
                v.y = acc[i][j + 1];
                v.z = acc[i][j + 2];
                v.w = acc[i][j + 3];
                *(float4*)(base + (((size_t)(b * 16 + h) * TSEQ + t) * HD + d)) = v;
            }
        }
    }
}

// ---------------------------------------------------------------------------
// In-place RoPE on g_q and g_k. One warp per (bh, t).
// ---------------------------------------------------------------------------
__global__ __launch_bounds__(256)
void rope_inplace()
{
    int gw   = (blockIdx.x * blockDim.x + threadIdx.x) >> 5;
    int lane = threadIdx.x & 31;
    if (gw >= BHEADS * TSEQ) return;
    int bh = gw >> 11;
    int t  = gw & 2047;

    float freq = expf(-9.210340371976184f * (float)lane * (1.0f / 32.0f));
    float ang  = (float)t * freq;
    float s, c;
    sincosf(ang, &s, &c);

    size_t off = ((size_t)bh * TSEQ + t) * HD;

    float q1 = g_q[off + lane], q2 = g_q[off + lane + 32];
    g_q[off + lane]      = q1 * c - q2 * s;
    g_q[off + lane + 32] = q1 * s + q2 * c;

    float k1 = g_k[off + lane], k2 = g_k[off + lane + 32];
    g_k[off + lane]      = k1 * c - k2 * s;
    g_k[off + lane + 32] = k1 * s + k2 * c;
}

// ---------------------------------------------------------------------------
// Flash attention: BQ=128, BK=64, 256 threads.
// ---------------------------------------------------------------------------
#define FA_BQ 128
#define FA_BK 64
#define PSS   68

#define FA_SMEM_FLOATS (64*128 + 64*64 + 64*64 + 128*PSS)

extern __shared__ float fa_smem[];

__global__ __launch_bounds__(256)
void flash_attn2()
{
    float* Qs = fa_smem;             // [d][r]  64 x 128
    float* Ks = Qs + 64 * 128;       // [d][j]  64 x 64
    float* Vs = Ks + 64 * 64;        // [j][d]  64 x 64
    float* Ps = Vs + 64 * 64;        // [r][j]  128 x PSS

    const int bh   = blockIdx.y;
    const int qblk = gridDim.x - 1 - blockIdx.x;   // heavy blocks first
    const int q0   = qblk * FA_BQ;

    const float* Qh = g_q + (size_t)bh * TSEQ * HD;
    const float* Kh = g_k + (size_t)bh * TSEQ * HD;
    const float* Vh = g_v + (size_t)bh * TSEQ * HD;

    const int tid = threadIdx.x;
    const int tr  = tid >> 4;
    const int tc  = tid & 15;

    // Load Q tile transposed: Qs[d][r]
    {
        int r     = tid >> 1;
        int dbase = (tid & 1) * 32;
        const float* qp = Qh + (size_t)(q0 + r) * HD + dbase;
        #pragma unroll
        for (int j = 0; j < 32; j += 4) {
            float4 v = *(const float4*)(qp + j);
            Qs[(dbase + j + 0) * 128 + r] = v.x;
            Qs[(dbase + j + 1) * 128 + r] = v.y;
            Qs[(dbase + j + 2) * 128 + r] = v.z;
            Qs[(dbase + j + 3) * 128 + r] = v.w;
        }
    }

    float oacc[8][4];
    float m[8], l[8];
    #pragma unroll
    for (int i = 0; i < 8; i++) {
        m[i] = -INFINITY; l[i] = 0.f;
        #pragma unroll
        for (int j = 0; j < 4; j++) oacc[i][j] = 0.f;
    }

    const int ntiles = 2 * qblk + 2;
    for (int t = 0; t < ntiles; t++) {
        const int k0 = t * FA_BK;

        // Load K tile transposed (Ks[d][j]) and V tile straight (Vs[j][d])
        {
            int j     = tid >> 2;
            int dbase = (tid & 3) * 16;
            const float* kp = Kh + (size_t)(k0 + j) * HD + dbase;
            const float* vp = Vh + (size_t)(k0 + j) * HD + dbase;
            #pragma unroll
            for (int d = 0; d < 16; d += 4) {
                float4 kv = *(const float4*)(kp + d);
                Ks[(dbase + d + 0) * 64 + j] = kv.x;
                Ks[(dbase + d + 1) * 64 + j] = kv.y;
                Ks[(dbase + d + 2) * 64 + j] = kv.z;
                Ks[(dbase + d + 3) * 64 + j] = kv.w;
                *(float4*)(Vs + j * 64 + dbase + d) = *(const float4*)(vp + d);
            }
        }
        __syncthreads();

        // ---- S = Q @ K^T ----
        float sacc[8][4];
        #pragma unroll
        for (int i = 0; i < 8; i++)
            #pragma unroll
            for (int j = 0; j < 4; j++) sacc[i][j] = 0.f;

        #pragma unroll 8
        for (int kk = 0; kk < 64; kk++) {
            float4 qa = *(const float4*)(Qs + kk * 128 + tr * 8);
            float4 qb = *(const float4*)(Qs + kk * 128 + tr * 8 + 4);
            float4 kr = *(const float4*)(Ks + kk * 64 + tc * 4);
            float qr[8] = {qa.x, qa.y, qa.z, qa.w, qb.x, qb.y, qb.z, qb.w};
            float kc[4] = {kr.x, kr.y, kr.z, kr.w};
            #pragma unroll
            for (int i = 0; i < 8; i++)
                #pragma unroll
                for (int j = 0; j < 4; j++)
                    sacc[i][j] = fmaf(qr[i], kc[j], sacc[i][j]);
        }

        // ---- scale + causal mask ----
        const bool need_mask = (k0 + FA_BK - 1 > q0);
        #pragma unroll
        for (int i = 0; i < 8; i++) {
            int grow = q0 + tr * 8 + i;
            #pragma unroll
            for (int j = 0; j < 4; j++) {
                float s = sacc[i][j] * ATT_SCALE;
                if (need_mask && (k0 + tc * 4 + j > grow)) s = -INFINITY;
                sacc[i][j] = s;
            }
        }

        // ---- online softmax ----
        #pragma unroll
        for (int i = 0; i < 8; i++) {
            float rmax = fmaxf(fmaxf(sacc[i][0], sacc[i][1]),
                               fmaxf(sacc[i][2], sacc[i][3]));
            rmax = fmaxf(rmax, __shfl_xor_sync(0xffffffffu, rmax, 1));
            rmax = fmaxf(rmax, __shfl_xor_sync(0xffffffffu, rmax, 2));
            rmax = fmaxf(rmax, __shfl_xor_sync(0xffffffffu, rmax, 4));
            rmax = fmaxf(rmax, __shfl_xor_sync(0xffffffffu, rmax, 8));

            float mnew = fmaxf(m[i], rmax);
            float resc = __expf(m[i] - mnew);
            m[i] = mnew;

            float p0 = __expf(sacc[i][0] - mnew);
            float p1 = __expf(sacc[i][1] - mnew);
            float p2 = __expf(sacc[i][2] - mnew);
            float p3 = __expf(sacc[i][3] - mnew);
            float psum = (p0 + p1) + (p2 + p3);
            psum += __shfl_xor_sync(0xffffffffu, psum, 1);
            psum += __shfl_xor_sync(0xffffffffu, psum, 2);
            psum += __shfl_xor_sync(0xffffffffu, psum, 4);
            psum += __shfl_xor_sync(0xffffffffu, psum, 8);

            l[i] = l[i] * resc + psum;
            #pragma unroll
            for (int j = 0; j < 4; j++) oacc[i][j] *= resc;

            float4 pv = make_float4(p0, p1, p2, p3);
            *(float4*)(Ps + (tr * 8 + i) * PSS + tc * 4) = pv;
        }
        __syncthreads();

        // ---- O += P @ V, float4 P reads ----
        #pragma unroll 2
        for (int j4 = 0; j4 < 64; j4 += 4) {
            float4 v0 = *(const float4*)(Vs + (j4 + 0) * 64 + tc * 4);
            float4 v1 = *(const float4*)(Vs + (j4 + 1) * 64 + tc * 4);
            float4 v2 = *(const float4*)(Vs + (j4 + 2) * 64 + tc * 4);
            float4 v3 = *(const float4*)(Vs + (j4 + 3) * 64 + tc * 4);
            #pragma unroll
            for (int i = 0; i < 8; i++) {
                float4 p = *(const float4*)(Ps + (tr * 8 + i) * PSS + j4);
                oacc[i][0] = fmaf(p.x, v0.x, oacc[i][0]);
                oacc[i][1] = fmaf(p.x, v0.y, oacc[i][1]);
                oacc[i][2] = fmaf(p.x, v0.z, oacc[i][2]);
                oacc[i][3] = fmaf(p.x, v0.w, oacc[i][3]);
                oacc[i][0] = fmaf(p.y, v1.x, oacc[i][0]);
                oacc[i][1] = fmaf(p.y, v1.y, oacc[i][1]);
                oacc[i][2] = fmaf(p.y, v1.z, oacc[i][2]);
                oacc[i][3] = fmaf(p.y, v1.w, oacc[i][3]);
                oacc[i][0] = fmaf(p.z, v2.x, oacc[i][0]);
                oacc[i][1] = fmaf(p.z, v2.y, oacc[i][1]);
                oacc[i][2] = fmaf(p.z, v2.z, oacc[i][2]);
                oacc[i][3] = fmaf(p.z, v2.w, oacc[i][3]);
                oacc[i][0] = fmaf(p.w, v3.x, oacc[i][0]);
                oacc[i][1] = fmaf(p.w, v3.y, oacc[i][1]);
                oacc[i][2] = fmaf(p.w, v3.z, oacc[i][2]);
                oacc[i][3] = fmaf(p.w, v3.w, oacc[i][3]);
            }
        }
        __syncthreads();
    }

    // ---- epilogue ----
    const int b = bh >> 4, h = bh & 15;
    #pragma unroll
    for (int i = 0; i < 8; i++) {
        float inv = 1.0f / l[i];
        int grow = q0 + tr * 8 + i;
        float* op = g_o + ((size_t)(b * TSEQ) + grow) * DIM + h * HD + tc * 4;
        float4 v;
        v.x = oacc[i][0] * inv;
        v.y = oacc[i][1] * inv;
        v.z = oacc[i][2] * inv;
        v.w = oacc[i][3] * inv;
        *(float4*)op = v;
    }
}

// ---------------------------------------------------------------------------
extern "C" void kernel_launch(void* const* d_in, const int* in_sizes, int n_in,
                              void* d_out, int out_size)
{
    const float* x      = (const float*)d_in[0];
    const float* w_qkv  = (const float*)d_in[1];
    const float* w_proj = (const float*)d_in[2];
    const float* b_proj = (const float*)d_in[3];
    float* out = (float*)d_out;

    float* o_p = nullptr;
    cudaGetSymbolAddress((void**)&o_p, g_o);

    // 1) qkv = x @ w_qkv, scattered directly into g_q/g_k/g_v
    dim3 g1(QKV_N / 128, TOKENS / 128);
    sgemm_db<<<g1, 256>>>(x, w_qkv, nullptr, nullptr, QKV_N, DIM, 1);

    // 2) rope in-place on q, k
    int nwarps = BHEADS * TSEQ;
    rope_inplace<<<(nwarps * 32 + 255) / 256, 256>>>();

    // 3) flash attention
    size_t fa_smem_bytes = FA_SMEM_FLOATS * sizeof(float);
    cudaFuncSetAttribute(flash_attn2,
                         cudaFuncAttributeMaxDynamicSharedMemorySize,
                         (int)fa_smem_bytes);
    flash_attn2<<<dim3(TSEQ / FA_BQ, BHEADS), 256, fa_smem_bytes>>>();

    // 4) out = g_o @ w_proj + b_proj
    dim3 g2(DIM / 128, TOKENS / 128);
    sgemm_db<<<g2, 256>>>(o_p, w_proj, out, b_proj, DIM, DIM, 0);
}

// round 5
// speedup vs baseline: 2.7671x; 1.2363x over previous
#include <cuda_runtime.h>
#include <cuda_bf16.h>
#include <stdint.h>
#include <math.h>

#define TOKENS 4096
#define DIM    1024
#define QKV_N  3072
#define NH     16
#define HD     64
#define TSEQ   2048
#define BHEADS 32
#define ATT_SCALE 0.125f

// Scratch (static device globals — no allocation in kernel_launch)
__device__ float g_q[BHEADS * TSEQ * HD];   // [bh][t][d]
__device__ float g_k[BHEADS * TSEQ * HD];
__device__ float g_v[BHEADS * TSEQ * HD];
__device__ float g_o[TOKENS * DIM];         // token-major

// ---------------------------------------------------------------------------
// bf16x3 split-GEMM on tensor cores.
// C = A@B in ~fp32 accuracy via A=Ah+Al, B=Bh+Bl, C ~= AhBh + AhBl + AlBh.
// Tile 128x128, BK=32, 256 threads (8 warps, each 64x32 via m16n8k16 mma).
// epi=0: C=A@B+bias (row-major). epi=1: scatter into g_q/g_k/g_v per head.
// ---------------------------------------------------------------------------
__device__ __forceinline__ void mma_bf16(float c[4],
                                         const unsigned int a[4],
                                         const unsigned int b[2])
{
    asm volatile(
        "mma.sync.aligned.m16n8k16.row.col.f32.bf16.bf16.f32 "
        "{%0,%1,%2,%3}, {%4,%5,%6,%7}, {%8,%9}, {%0,%1,%2,%3};"
        : "+f"(c[0]), "+f"(c[1]), "+f"(c[2]), "+f"(c[3])
        : "r"(a[0]), "r"(a[1]), "r"(a[2]), "r"(a[3]),
          "r"(b[0]), "r"(b[1]));
}

__device__ __forceinline__ void split_pack(float x0, float x1,
                                           unsigned int& hi, unsigned int& lo)
{
    __nv_bfloat162 H = __floats2bfloat162_rn(x0, x1);
    float2 hf = __bfloat1622float2(H);
    __nv_bfloat162 L = __floats2bfloat162_rn(x0 - hf.x, x1 - hf.y);
    hi = *(unsigned int*)&H;
    lo = *(unsigned int*)&L;
}

__global__ __launch_bounds__(256)
void mma_gemm(const float* __restrict__ A, const float* __restrict__ B,
              float* __restrict__ C, const float* __restrict__ bias,
              int N, int K, int epi)
{
    // smem: [k2][m/n], stride 132 (conflict-free for frag loads & stores)
    __shared__ unsigned int Ah[16][132], Al[16][132];
    __shared__ unsigned int Bh[16][132], Bl[16][132];

    const int tid  = threadIdx.x;
    const int wid  = tid >> 5;
    const int lane = tid & 31;
    const int r8   = lane >> 2;   // 0..7
    const int c4   = lane & 3;    // 0..3
    const int wm   = (wid >> 2) * 64;   // warp row base in tile
    const int wn   = (wid & 3) * 32;    // warp col base in tile
    const int brow = blockIdx.y, bcol = blockIdx.x;

    // A loader: row a_row (0..127), k-segment a_ks (0 or 16)
    const int a_row = tid & 127;
    const int a_ks  = (tid >> 7) * 16;
    const float* Ap = A + (size_t)(brow * 128 + a_row) * K + a_ks;

    // B loader: column b_n (0..127), k2-half b_kh (0 or 8)
    const int b_n  = tid & 127;
    const int b_kh = (tid >> 7) * 8;
    const float* Bp = B + bcol * 128 + b_n;

    float acc[4][4][4];
    #pragma unroll
    for (int i = 0; i < 4; i++)
        #pragma unroll
        for (int j = 0; j < 4; j++)
            #pragma unroll
            for (int r = 0; r < 4; r++) acc[i][j][r] = 0.f;

    float aL[16], bL[16];

    // prefetch k0 = 0
    #pragma unroll
    for (int q = 0; q < 4; q++)
        *(float4*)&aL[q * 4] = *(const float4*)(Ap + q * 4);
    #pragma unroll
    for (int i = 0; i < 8; i++) {
        int gk = 2 * (b_kh + i);
        bL[2 * i]     = Bp[(size_t)gk * N];
        bL[2 * i + 1] = Bp[(size_t)(gk + 1) * N];
    }

    for (int k0 = 0; k0 < K; k0 += 32) {
        // stage into smem with bf16 hi/lo split
        #pragma unroll
        for (int j = 0; j < 8; j++) {
            unsigned int hi, lo;
            split_pack(aL[2 * j], aL[2 * j + 1], hi, lo);
            Ah[(a_ks >> 1) + j][a_row] = hi;
            Al[(a_ks >> 1) + j][a_row] = lo;
        }
        #pragma unroll
        for (int i = 0; i < 8; i++) {
            unsigned int hi, lo;
            split_pack(bL[2 * i], bL[2 * i + 1], hi, lo);
            Bh[b_kh + i][b_n] = hi;
            Bl[b_kh + i][b_n] = lo;
        }
        __syncthreads();

        // prefetch next stage
        if (k0 + 32 < K) {
            #pragma unroll
            for (int q = 0; q < 4; q++)
                *(float4*)&aL[q * 4] = *(const float4*)(Ap + k0 + 32 + q * 4);
            #pragma unroll
            for (int i = 0; i < 8; i++) {
                int gk = k0 + 32 + 2 * (b_kh + i);
                bL[2 * i]     = Bp[(size_t)gk * N];
                bL[2 * i + 1] = Bp[(size_t)(gk + 1) * N];
            }
        }

        // compute: two k16 sub-steps
        #pragma unroll
        for (int kk = 0; kk < 16; kk += 8) {
            unsigned int ah[4][4], al[4][4], bh[4][2], bl[4][2];
            #pragma unroll
            for (int mf = 0; mf < 4; mf++) {
                int m = wm + mf * 16 + r8;
                ah[mf][0] = Ah[kk + c4][m];
                ah[mf][1] = Ah[kk + c4][m + 8];
                ah[mf][2] = Ah[kk + 4 + c4][m];
                ah[mf][3] = Ah[kk + 4 + c4][m + 8];
                al[mf][0] = Al[kk + c4][m];
                al[mf][1] = Al[kk + c4][m + 8];
                al[mf][2] = Al[kk + 4 + c4][m];
                al[mf][3] = Al[kk + 4 + c4][m + 8];
            }
            #pragma unroll
            for (int nf = 0; nf < 4; nf++) {
                int n = wn + nf * 8 + r8;
                bh[nf][0] = Bh[kk + c4][n];
                bh[nf][1] = Bh[kk + 4 + c4][n];
                bl[nf][0] = Bl[kk + c4][n];
                bl[nf][1] = Bl[kk + 4 + c4][n];
            }
            #pragma unroll
            for (int mf = 0; mf < 4; mf++)
                #pragma unroll
                for (int nf = 0; nf < 4; nf++)
                    mma_bf16(acc[mf][nf], ah[mf], bh[nf]);
            #pragma unroll
            for (int mf = 0; mf < 4; mf++)
                #pragma unroll
                for (int nf = 0; nf < 4; nf++)
                    mma_bf16(acc[mf][nf], ah[mf], bl[nf]);
            #pragma unroll
            for (int mf = 0; mf < 4; mf++)
                #pragma unroll
                for (int nf = 0; nf < 4; nf++)
                    mma_bf16(acc[mf][nf], al[mf], bh[nf]);
        }
        __syncthreads();
    }

    // epilogue
    if (!epi) {
        #pragma unroll
        for (int nf = 0; nf < 4; nf++) {
            const int cg = bcol * 128 + wn + nf * 8 + c4 * 2;
            float bx = bias ? bias[cg]     : 0.f;
            float by = bias ? bias[cg + 1] : 0.f;
            #pragma unroll
            for (int mf = 0; mf < 4; mf++) {
                const int rg = brow * 128 + wm + mf * 16 + r8;
                float2 v0 = make_float2(acc[mf][nf][0] + bx, acc[mf][nf][1] + by);
                float2 v1 = make_float2(acc[mf][nf][2] + bx, acc[mf][nf][3] + by);
                *(float2*)(C + (size_t)rg * N + cg)       = v0;
                *(float2*)(C + (size_t)(rg + 8) * N + cg) = v1;
            }
        }
    } else {
        #pragma unroll
        for (int nf = 0; nf < 4; nf++) {
            const int n_g   = bcol * 128 + wn + nf * 8 + c4 * 2;
            const int which = n_g >> 10;        // 0=q 1=k 2=v
            const int rmod  = n_g & 1023;
            const int h     = rmod >> 6;
            const int d     = rmod & 63;
            float* base = (which == 0) ? g_q : (which == 1) ? g_k : g_v;
            #pragma unroll
            for (int mf = 0; mf < 4; mf++) {
                const int m_g0 = brow * 128 + wm + mf * 16 + r8;
                #pragma unroll
                for (int half = 0; half < 2; half++) {
                    const int m_g = m_g0 + half * 8;
                    const int b   = m_g >> 11;
                    const int t   = m_g & 2047;
                    float2 v = make_float2(acc[mf][nf][half * 2],
                                           acc[mf][nf][half * 2 + 1]);
                    *(float2*)(base + (((size_t)(b * 16 + h) * TSEQ + t) * HD + d)) = v;
                }
            }
        }
    }
}

// ---------------------------------------------------------------------------
// In-place RoPE on g_q and g_k. One warp per (bh, t).
// ---------------------------------------------------------------------------
__global__ __launch_bounds__(256)
void rope_inplace()
{
    int gw   = (blockIdx.x * blockDim.x + threadIdx.x) >> 5;
    int lane = threadIdx.x & 31;
    if (gw >= BHEADS * TSEQ) return;
    int bh = gw >> 11;
    int t  = gw & 2047;

    float freq = expf(-9.210340371976184f * (float)lane * (1.0f / 32.0f));
    float ang  = (float)t * freq;
    float s, c;
    sincosf(ang, &s, &c);

    size_t off = ((size_t)bh * TSEQ + t) * HD;

    float q1 = g_q[off + lane], q2 = g_q[off + lane + 32];
    g_q[off + lane]      = q1 * c - q2 * s;
    g_q[off + lane + 32] = q1 * s + q2 * c;

    float k1 = g_k[off + lane], k2 = g_k[off + lane + 32];
    g_k[off + lane]      = k1 * c - k2 * s;
    g_k[off + lane + 32] = k1 * s + k2 * c;
}

// ---------------------------------------------------------------------------
// Flash attention: BQ=128, BK=64, 256 threads (fp32).
// ---------------------------------------------------------------------------
#define FA_BQ 128
#define FA_BK 64
#define PSS   68

#define FA_SMEM_FLOATS (64*128 + 64*64 + 64*64 + 128*PSS)

extern __shared__ float fa_smem[];

__global__ __launch_bounds__(256)
void flash_attn2()
{
    float* Qs = fa_smem;             // [d][r]  64 x 128
    float* Ks = Qs + 64 * 128;       // [d][j]  64 x 64
    float* Vs = Ks + 64 * 64;        // [j][d]  64 x 64
    float* Ps = Vs + 64 * 64;        // [r][j]  128 x PSS

    const int bh   = blockIdx.y;
    const int qblk = gridDim.x - 1 - blockIdx.x;
    const int q0   = qblk * FA_BQ;

    const float* Qh = g_q + (size_t)bh * TSEQ * HD;
    const float* Kh = g_k + (size_t)bh * TSEQ * HD;
    const float* Vh = g_v + (size_t)bh * TSEQ * HD;

    const int tid = threadIdx.x;
    const int tr  = tid >> 4;
    const int tc  = tid & 15;

    {
        int r     = tid >> 1;
        int dbase = (tid & 1) * 32;
        const float* qp = Qh + (size_t)(q0 + r) * HD + dbase;
        #pragma unroll
        for (int j = 0; j < 32; j += 4) {
            float4 v = *(const float4*)(qp + j);
            Qs[(dbase + j + 0) * 128 + r] = v.x;
            Qs[(dbase + j + 1) * 128 + r] = v.y;
            Qs[(dbase + j + 2) * 128 + r] = v.z;
            Qs[(dbase + j + 3) * 128 + r] = v.w;
        }
    }

    float oacc[8][4];
    float m[8], l[8];
    #pragma unroll
    for (int i = 0; i < 8; i++) {
        m[i] = -INFINITY; l[i] = 0.f;
        #pragma unroll
        for (int j = 0; j < 4; j++) oacc[i][j] = 0.f;
    }

    const int ntiles = 2 * qblk + 2;
    for (int t = 0; t < ntiles; t++) {
        const int k0 = t * FA_BK;

        {
            int j     = tid >> 2;
            int dbase = (tid & 3) * 16;
            const float* kp = Kh + (size_t)(k0 + j) * HD + dbase;
            const float* vp = Vh + (size_t)(k0 + j) * HD + dbase;
            #pragma unroll
            for (int d = 0; d < 16; d += 4) {
                float4 kv = *(const float4*)(kp + d);
                Ks[(dbase + d + 0) * 64 + j] = kv.x;
                Ks[(dbase + d + 1) * 64 + j] = kv.y;
                Ks[(dbase + d + 2) * 64 + j] = kv.z;
                Ks[(dbase + d + 3) * 64 + j] = kv.w;
                *(float4*)(Vs + j * 64 + dbase + d) = *(const float4*)(vp + d);
            }
        }
        __syncthreads();

        float sacc[8][4];
        #pragma unroll
        for (int i = 0; i < 8; i++)
            #pragma unroll
            for (int j = 0; j < 4; j++) sacc[i][j] = 0.f;

        #pragma unroll 8
        for (int kk = 0; kk < 64; kk++) {
            float4 qa = *(const float4*)(Qs + kk * 128 + tr * 8);
            float4 qb = *(const float4*)(Qs + kk * 128 + tr * 8 + 4);
            float4 kr = *(const float4*)(Ks + kk * 64 + tc * 4);
            float qr[8] = {qa.x, qa.y, qa.z, qa.w, qb.x, qb.y, qb.z, qb.w};
            float kc[4] = {kr.x, kr.y, kr.z, kr.w};
            #pragma unroll
            for (int i = 0; i < 8; i++)
                #pragma unroll
                for (int j = 0; j < 4; j++)
                    sacc[i][j] = fmaf(qr[i], kc[j], sacc[i][j]);
        }

        const bool need_mask = (k0 + FA_BK - 1 > q0);
        #pragma unroll
        for (int i = 0; i < 8; i++) {
            int grow = q0 + tr * 8 + i;
            #pragma unroll
            for (int j = 0; j < 4; j++) {
                float s = sacc[i][j] * ATT_SCALE;
                if (need_mask && (k0 + tc * 4 + j > grow)) s = -INFINITY;
                sacc[i][j] = s;
            }
        }

        #pragma unroll
        for (int i = 0; i < 8; i++) {
            float rmax = fmaxf(fmaxf(sacc[i][0], sacc[i][1]),
                               fmaxf(sacc[i][2], sacc[i][3]));
            rmax = fmaxf(rmax, __shfl_xor_sync(0xffffffffu, rmax, 1));
            rmax = fmaxf(rmax, __shfl_xor_sync(0xffffffffu, rmax, 2));
            rmax = fmaxf(rmax, __shfl_xor_sync(0xffffffffu, rmax, 4));
            rmax = fmaxf(rmax, __shfl_xor_sync(0xffffffffu, rmax, 8));

            float mnew = fmaxf(m[i], rmax);
            float resc = __expf(m[i] - mnew);
            m[i] = mnew;

            float p0 = __expf(sacc[i][0] - mnew);
            float p1 = __expf(sacc[i][1] - mnew);
            float p2 = __expf(sacc[i][2] - mnew);
            float p3 = __expf(sacc[i][3] - mnew);
            float psum = (p0 + p1) + (p2 + p3);
            psum += __shfl_xor_sync(0xffffffffu, psum, 1);
            psum += __shfl_xor_sync(0xffffffffu, psum, 2);
            psum += __shfl_xor_sync(0xffffffffu, psum, 4);
            psum += __shfl_xor_sync(0xffffffffu, psum, 8);

            l[i] = l[i] * resc + psum;
            #pragma unroll
            for (int j = 0; j < 4; j++) oacc[i][j] *= resc;

            float4 pv = make_float4(p0, p1, p2, p3);
            *(float4*)(Ps + (tr * 8 + i) * PSS + tc * 4) = pv;
        }
        __syncthreads();

        #pragma unroll 2
        for (int j4 = 0; j4 < 64; j4 += 4) {
            float4 v0 = *(const float4*)(Vs + (j4 + 0) * 64 + tc * 4);
            float4 v1 = *(const float4*)(Vs + (j4 + 1) * 64 + tc * 4);
            float4 v2 = *(const float4*)(Vs + (j4 + 2) * 64 + tc * 4);
            float4 v3 = *(const float4*)(Vs + (j4 + 3) * 64 + tc * 4);
            #pragma unroll
            for (int i = 0; i < 8; i++) {
                float4 p = *(const float4*)(Ps + (tr * 8 + i) * PSS + j4);
                oacc[i][0] = fmaf(p.x, v0.x, oacc[i][0]);
                oacc[i][1] = fmaf(p.x, v0.y, oacc[i][1]);
                oacc[i][2] = fmaf(p.x, v0.z, oacc[i][2]);
                oacc[i][3] = fmaf(p.x, v0.w, oacc[i][3]);
                oacc[i][0] = fmaf(p.y, v1.x, oacc[i][0]);
                oacc[i][1] = fmaf(p.y, v1.y, oacc[i][1]);
                oacc[i][2] = fmaf(p.y, v1.z, oacc[i][2]);
                oacc[i][3] = fmaf(p.y, v1.w, oacc[i][3]);
                oacc[i][0] = fmaf(p.z, v2.x, oacc[i][0]);
                oacc[i][1] = fmaf(p.z, v2.y, oacc[i][1]);
                oacc[i][2] = fmaf(p.z, v2.z, oacc[i][2]);
                oacc[i][3] = fmaf(p.z, v2.w, oacc[i][3]);
                oacc[i][0] = fmaf(p.w, v3.x, oacc[i][0]);
                oacc[i][1] = fmaf(p.w, v3.y, oacc[i][1]);
                oacc[i][2] = fmaf(p.w, v3.z, oacc[i][2]);
                oacc[i][3] = fmaf(p.w, v3.w, oacc[i][3]);
            }
        }
        __syncthreads();
    }

    const int b = bh >> 4, h = bh & 15;
    #pragma unroll
    for (int i = 0; i < 8; i++) {
        float inv = 1.0f / l[i];
        int grow = q0 + tr * 8 + i;
        float* op = g_o + ((size_t)(b * TSEQ) + grow) * DIM + h * HD + tc * 4;
        float4 v;
        v.x = oacc[i][0] * inv;
        v.y = oacc[i][1] * inv;
        v.z = oacc[i][2] * inv;
        v.w = oacc[i][3] * inv;
        *(float4*)op = v;
    }
}

// ---------------------------------------------------------------------------
extern "C" void kernel_launch(void* const* d_in, const int* in_sizes, int n_in,
                              void* d_out, int out_size)
{
    const float* x      = (const float*)d_in[0];
    const float* w_qkv  = (const float*)d_in[1];
    const float* w_proj = (const float*)d_in[2];
    const float* b_proj = (const float*)d_in[3];
    float* out = (float*)d_out;

    float* o_p = nullptr;
    cudaGetSymbolAddress((void**)&o_p, g_o);

    // 1) qkv = x @ w_qkv, scattered into g_q/g_k/g_v (tensor cores, bf16x3)
    dim3 g1(QKV_N / 128, TOKENS / 128);
    mma_gemm<<<g1, 256>>>(x, w_qkv, nullptr, nullptr, QKV_N, DIM, 1);

    // 2) rope in-place on q, k
    int nwarps = BHEADS * TSEQ;
    rope_inplace<<<(nwarps * 32 + 255) / 256, 256>>>();

    // 3) flash attention (fp32)
    size_t fa_smem_bytes = FA_SMEM_FLOATS * sizeof(float);
    cudaFuncSetAttribute(flash_attn2,
                         cudaFuncAttributeMaxDynamicSharedMemorySize,
                         (int)fa_smem_bytes);
    flash_attn2<<<dim3(TSEQ / FA_BQ, BHEADS), 256, fa_smem_bytes>>>();

    // 4) out = g_o @ w_proj + b_proj (tensor cores, bf16x3)
    dim3 g2(DIM / 128, TOKENS / 128);
    mma_gemm<<<g2, 256>>>(o_p, w_proj, out, b_proj, DIM, DIM, 0);
}